// round 15
// baseline (speedup 1.0000x reference)
#include <cuda_runtime.h>
#include <cuda_fp16.h>
#include <cstdint>

#define N_NODES 100000
#define E_EDGES 3200000
#define NFEAT   512
#define NHID    256
#define NCLASS  64
#define K_HOPS  10
#define SLOTS   96          // padded neighbor slots (Poisson(32); P(>96) ~ 1e-17/node)

#define SLABSZ  ((size_t)(N_NODES + 1) * NCLASS)   // halves per u-slab (+1 zero row)
#define ZOFF    (N_NODES * 128)                    // byte offset of the zero row

// ---------------- scratch (device globals) ----------------
__device__ __align__(256) __half g_h1[(size_t)N_NODES * NHID];        // 51.2 MB
__device__ __align__(256) __half g_us[(size_t)(K_HOPS + 1) * SLABSZ]; // u_k slabs
__device__ int g_deg[N_NODES];
__device__ __align__(16) int g_col[(size_t)N_NODES * SLOTS + 128];    // byte offsets

// ---------------- side stream for build-chain overlap (created pre-main) ------
struct SideStream {
    cudaStream_t s1;
    cudaEvent_t  evA, evB;
    SideStream() {
        cudaStreamCreateWithFlags(&s1, cudaStreamNonBlocking);
        cudaEventCreateWithFlags(&evA, cudaEventDisableTiming);
        cudaEventCreateWithFlags(&evB, cudaEventDisableTiming);
    }
};
static SideStream g_ss;

// ---------------- fill: pad all slots with zero-row offset; reset deg ----------
__global__ void fill_kernel() {
    int i = blockIdx.x * blockDim.x + threadIdx.x;
    const int n4 = N_NODES * SLOTS / 4;
    if (i < n4) ((int4*)g_col)[i] = make_int4(ZOFF, ZOFF, ZOFF, ZOFF);
    if (i < N_NODES) g_deg[i] = 0;
}

// ---------------- graph build: 4 edges per thread (int4 loads) ----------------
__global__ void build_kernel(const int* __restrict__ ei) {
    int e4 = (blockIdx.x * blockDim.x + threadIdx.x) * 4;
    if (e4 < E_EDGES) {
        int4 s = *(const int4*)&ei[e4];
        int4 d = *(const int4*)&ei[(size_t)E_EDGES + e4];
        int p;
        p = atomicAdd(&g_deg[d.x], 1);
        if (p < SLOTS) g_col[(size_t)d.x * SLOTS + p] = s.x << 7;
        p = atomicAdd(&g_deg[d.y], 1);
        if (p < SLOTS) g_col[(size_t)d.y * SLOTS + p] = s.y << 7;
        p = atomicAdd(&g_deg[d.z], 1);
        if (p < SLOTS) g_col[(size_t)d.z * SLOTS + p] = s.z << 7;
        p = atomicAdd(&g_deg[d.w], 1);
        if (p < SLOTS) g_col[(size_t)d.w * SLOTS + p] = s.w << 7;
    }
}

// ---------------- cp.async helpers ----------------
__device__ __forceinline__ void cpa16(uint32_t dst, const void* src, bool pred) {
    int sz = pred ? 16 : 0;
    asm volatile("cp.async.cg.shared.global [%0], [%1], 16, %2;\n"
                 :: "r"(dst), "l"(src), "r"(sz));
}
__device__ __forceinline__ void cpa_commit() {
    asm volatile("cp.async.commit_group;\n");
}
template <int N>
__device__ __forceinline__ void cpa_wait() {
    asm volatile("cp.async.wait_group %0;\n" :: "n"(N));
}
__device__ __forceinline__ uint32_t smem_u32(const void* p) {
    return (uint32_t)__cvta_generic_to_shared(p);
}

// ---------------- tf32 mma ----------------
__device__ __forceinline__ void mma_tf32(float* d, const unsigned* a,
                                         unsigned b0, unsigned b1) {
    asm volatile(
        "mma.sync.aligned.m16n8k8.row.col.f32.tf32.tf32.f32 "
        "{%0,%1,%2,%3},{%4,%5,%6,%7},{%8,%9},{%0,%1,%2,%3};"
        : "+f"(d[0]), "+f"(d[1]), "+f"(d[2]), "+f"(d[3])
        : "r"(a[0]), "r"(a[1]), "r"(a[2]), "r"(a[3]), "r"(b0), "r"(b1));
}

// ---------------- 3-stage cp.async tf32 GEMM ----------------
// SWAP_GRID: blockIdx.y selects the M-block, blockIdx.x the N-block. With
// grid=(Nblocks, Mblocks), CTAs sharing an A-row-block are launch-adjacent,
// so the second read of the A panel hits L2.
template <int BN, int NFRAG, bool RELU, bool A_HALF, bool WRITE_C, bool HALF_C,
          bool WRITE_U, bool SWAP_GRID>
__global__ __launch_bounds__(256) void tc_gemm_kernel(
    const void* __restrict__ Av, const float* __restrict__ B,
    const float* __restrict__ bias, void* __restrict__ Cv,
    __half* __restrict__ U, int M, int N, int K)
{
    constexpr int BM = 128, BK = 32;
    constexpr int ASTR  = A_HALF ? 40 : 36;
    constexpr int BSTR  = BN + 8;
    constexpr int ABYTES = BM * ASTR * (A_HALF ? 2 : 4);
    constexpr int BBYTES = BK * BSTR * 4;
    constexpr int STAGE  = ABYTES + BBYTES;
    extern __shared__ char dynsmem[];

    int tid  = threadIdx.x;
    int lane = tid & 31;
    int wid  = tid >> 5;
    int warpM = (wid & 3) * 32;
    int warpN = (wid >> 2) * (BN / 2);
    int blockRow = (SWAP_GRID ? blockIdx.y : blockIdx.x) * BM;
    int blockCol = (SWAP_GRID ? blockIdx.x : blockIdx.y) * BN;

    const float*  Af = (const float*)Av;
    const __half* Ah = (const __half*)Av;

    float acc[2][NFRAG][4];
    #pragma unroll
    for (int mf = 0; mf < 2; mf++)
        #pragma unroll
        for (int nf = 0; nf < NFRAG; nf++)
            #pragma unroll
            for (int j = 0; j < 4; j++) acc[mf][nf][j] = 0.f;

    const int T = K / BK;

    auto issue = [&](int s, int k0) {
        char* sb = dynsmem + s * STAGE;
        if (A_HALF) {
            __half* As = (__half*)sb;
            #pragma unroll
            for (int j = 0; j < 2; j++) {
                int id  = tid + 256 * j;
                int row = id >> 2, cc = id & 3;
                int grow = blockRow + row;
                cpa16(smem_u32(&As[row * ASTR + cc * 8]),
                      &Ah[(size_t)grow * K + k0 + cc * 8], grow < M);
            }
        } else {
            float* As = (float*)sb;
            #pragma unroll
            for (int j = 0; j < 4; j++) {
                int id  = tid + 256 * j;
                int row = id >> 3, cc = id & 7;
                int grow = blockRow + row;
                cpa16(smem_u32(&As[row * ASTR + cc * 4]),
                      &Af[(size_t)grow * K + k0 + cc * 4], grow < M);
            }
        }
        float* Bs = (float*)(sb + ABYTES);
        constexpr int cpr = BN / 4;
        constexpr int per = (BK * cpr) / 256;
        #pragma unroll
        for (int j = 0; j < per; j++) {
            int id  = tid + 256 * j;
            int row = id / cpr, cc = id % cpr;
            cpa16(smem_u32(&Bs[row * BSTR + cc * 4]),
                  &B[(size_t)(k0 + row) * N + blockCol + cc * 4], true);
        }
        cpa_commit();
    };

    issue(0, 0);
    issue(1, BK);

    int cur = 0;
    for (int t = 0; t < T; t++) {
        if (t + 1 == T) cpa_wait<0>(); else cpa_wait<1>();
        __syncthreads();
        if (t + 2 < T) {
            int nx = cur + 2; if (nx >= 3) nx -= 3;
            issue(nx, (t + 2) * BK);
        }

        char* sb = dynsmem + cur * STAGE;
        const __half* AsH = (const __half*)sb;
        const float*  AsF = (const float*)sb;
        const float*  Bs  = (const float*)(sb + ABYTES);

        #pragma unroll
        for (int ks = 0; ks < 4; ks++) {
            int kb = ks * 8;
            int ar = warpM + (lane >> 2);
            int ac = kb + (lane & 3);
            unsigned a[2][4];
            #pragma unroll
            for (int mf = 0; mf < 2; mf++) {
                int r = ar + mf * 16;
                if (A_HALF) {
                    a[mf][0] = __float_as_uint(__half2float(AsH[r * ASTR + ac]));
                    a[mf][1] = __float_as_uint(__half2float(AsH[(r + 8) * ASTR + ac]));
                    a[mf][2] = __float_as_uint(__half2float(AsH[r * ASTR + ac + 4]));
                    a[mf][3] = __float_as_uint(__half2float(AsH[(r + 8) * ASTR + ac + 4]));
                } else {
                    a[mf][0] = __float_as_uint(AsF[r * ASTR + ac]);
                    a[mf][1] = __float_as_uint(AsF[(r + 8) * ASTR + ac]);
                    a[mf][2] = __float_as_uint(AsF[r * ASTR + ac + 4]);
                    a[mf][3] = __float_as_uint(AsF[(r + 8) * ASTR + ac + 4]);
                }
            }
            int br = kb + (lane & 3);
            #pragma unroll
            for (int nf = 0; nf < NFRAG; nf++) {
                int bc = warpN + nf * 8 + (lane >> 2);
                unsigned b0 = __float_as_uint(Bs[br * BSTR + bc]);
                unsigned b1 = __float_as_uint(Bs[(br + 4) * BSTR + bc]);
                mma_tf32(acc[0][nf], a[0], b0, b1);
                mma_tf32(acc[1][nf], a[1], b0, b1);
            }
        }
        cur++; if (cur >= 3) cur -= 3;
    }

    #pragma unroll
    for (int mf = 0; mf < 2; mf++) {
        int row0 = blockRow + warpM + mf * 16 + (lane >> 2);
        float di0 = 0.f, di1 = 0.f;
        if (WRITE_U) {
            if (row0 < M)     di0 = rsqrtf((float)(g_deg[row0] + 1));
            if (row0 + 8 < M) di1 = rsqrtf((float)(g_deg[row0 + 8] + 1));
        }
        #pragma unroll
        for (int nf = 0; nf < NFRAG; nf++) {
            int col = blockCol + warpN + nf * 8 + 2 * (lane & 3);
            float2 bvx = __ldg((const float2*)&bias[col]);
            float2 o0, o1;
            o0.x = acc[mf][nf][0] + bvx.x; o0.y = acc[mf][nf][1] + bvx.y;
            o1.x = acc[mf][nf][2] + bvx.x; o1.y = acc[mf][nf][3] + bvx.y;
            if (RELU) {
                o0.x = fmaxf(o0.x, 0.f); o0.y = fmaxf(o0.y, 0.f);
                o1.x = fmaxf(o1.x, 0.f); o1.y = fmaxf(o1.y, 0.f);
            }
            if (WRITE_C) {
                if (HALF_C) {
                    __half* Ch = (__half*)Cv;
                    if (row0 < M)
                        *(__half2*)&Ch[(size_t)row0 * N + col] = __floats2half2_rn(o0.x, o0.y);
                    if (row0 + 8 < M)
                        *(__half2*)&Ch[(size_t)(row0 + 8) * N + col] = __floats2half2_rn(o1.x, o1.y);
                } else {
                    float* Cf = (float*)Cv;
                    if (row0 < M)     *(float2*)&Cf[(size_t)row0 * N + col]       = o0;
                    if (row0 + 8 < M) *(float2*)&Cf[(size_t)(row0 + 8) * N + col] = o1;
                }
            }
            if (WRITE_U) {
                if (row0 < M)
                    *(__half2*)&U[(size_t)row0 * N + col] =
                        __floats2half2_rn(di0 * o0.x, di0 * o0.y);
                if (row0 + 8 < M)
                    *(__half2*)&U[(size_t)(row0 + 8) * N + col] =
                        __floats2half2_rn(di1 * o1.x, di1 * o1.y);
            }
        }
    }
}

// ---------------- one hop: 4 rows per warp, uint4 per lane --------------------
__global__ __launch_bounds__(256) void propagate_kernel(
    const __half* __restrict__ uin, __half* __restrict__ uout)
{
    int gwarp = (blockIdx.x * blockDim.x + threadIdx.x) >> 5;
    int lane  = threadIdx.x & 31;
    int g     = lane >> 3;
    int lig   = lane & 7;
    int row   = gwarp * 4 + g;
    if (row >= N_NODES) return;

    int deg = g_deg[row];
    if (deg > SLOTS) deg = SLOTS;

    const char* base = (const char*)uin + lig * 16;

    uint4 sv = __ldg((const uint4*)(base + (size_t)row * 128));   // self term
    __half2 a0 = ((__half2*)&sv)[0], a1 = ((__half2*)&sv)[1];
    __half2 a2 = ((__half2*)&sv)[2], a3 = ((__half2*)&sv)[3];
    __half2 z  = __float2half2_rn(0.f);
    __half2 b0 = z, b1 = z, b2 = z, b3 = z;

    int md = deg;
    md = max(md, __shfl_xor_sync(0xffffffffu, md, 8));
    md = max(md, __shfl_xor_sync(0xffffffffu, md, 16));

    const int4* cp = (const int4*)&g_col[(size_t)row * SLOTS];
    int nchunks = (md + 3) >> 2;
    for (int c = 0; c < nchunks; c++) {
        int4 off = __ldg(&cp[c]);
        uint4 v0 = __ldg((const uint4*)(base + off.x));
        uint4 v1 = __ldg((const uint4*)(base + off.y));
        uint4 v2 = __ldg((const uint4*)(base + off.z));
        uint4 v3 = __ldg((const uint4*)(base + off.w));
        a0 = __hadd2(a0, ((__half2*)&v0)[0]); a1 = __hadd2(a1, ((__half2*)&v0)[1]);
        a2 = __hadd2(a2, ((__half2*)&v0)[2]); a3 = __hadd2(a3, ((__half2*)&v0)[3]);
        b0 = __hadd2(b0, ((__half2*)&v1)[0]); b1 = __hadd2(b1, ((__half2*)&v1)[1]);
        b2 = __hadd2(b2, ((__half2*)&v1)[2]); b3 = __hadd2(b3, ((__half2*)&v1)[3]);
        a0 = __hadd2(a0, ((__half2*)&v2)[0]); a1 = __hadd2(a1, ((__half2*)&v2)[1]);
        a2 = __hadd2(a2, ((__half2*)&v2)[2]); a3 = __hadd2(a3, ((__half2*)&v2)[3]);
        b0 = __hadd2(b0, ((__half2*)&v3)[0]); b1 = __hadd2(b1, ((__half2*)&v3)[1]);
        b2 = __hadd2(b2, ((__half2*)&v3)[2]); b3 = __hadd2(b3, ((__half2*)&v3)[3]);
    }

    __half2 di2 = __float2half2_rn(1.0f / (float)(deg + 1));
    uint4 ov;
    ((__half2*)&ov)[0] = __hmul2(__hadd2(a0, b0), di2);
    ((__half2*)&ov)[1] = __hmul2(__hadd2(a1, b1), di2);
    ((__half2*)&ov)[2] = __hmul2(__hadd2(a2, b2), di2);
    ((__half2*)&ov)[3] = __hmul2(__hadd2(a3, b3), di2);
    *(uint4*)((char*)uout + (size_t)row * 128 + lig * 16) = ov;
}

// ---------------- finalize: logits = sqrt(deg+1)*sum temp_k u_k; log_softmax ----
__global__ __launch_bounds__(256) void finalize_kernel(
    const float* __restrict__ temp, float* __restrict__ out)
{
    int gid  = blockIdx.x * blockDim.x + threadIdx.x;
    int row  = gid >> 5;
    int lane = gid & 31;
    if (row >= N_NODES) return;

    float sc = sqrtf((float)(g_deg[row] + 1));

    const __half2* us2 = (const __half2*)g_us;
    const size_t SLAB2 = SLABSZ / 2;
    float hx = 0.f, hy = 0.f;
    #pragma unroll
    for (int k = 0; k <= K_HOPS; k++) {
        float2 v = __half22float2(
            __ldg(&us2[(size_t)k * SLAB2 + (size_t)row * 32 + lane]));
        float t = __ldg(&temp[k]);
        hx += t * v.x; hy += t * v.y;
    }
    hx *= sc; hy *= sc;

    float m = fmaxf(hx, hy);
    #pragma unroll
    for (int o = 16; o; o >>= 1) m = fmaxf(m, __shfl_xor_sync(0xffffffffu, m, o));
    float s = expf(hx - m) + expf(hy - m);
    #pragma unroll
    for (int o = 16; o; o >>= 1) s += __shfl_xor_sync(0xffffffffu, s, o);
    float lse = m + logf(s);
    ((float2*)out)[(size_t)row * 32 + lane] = make_float2(hx - lse, hy - lse);
}

// ---------------- launch ----------------
extern "C" void kernel_launch(void* const* d_in, const int* in_sizes, int n_in,
                              void* d_out, int out_size) {
    const float* x    = (const float*)d_in[0];
    const int*   ei   = (const int*)d_in[1];    // int32 (JAX x64 disabled)
    const float* W1   = (const float*)d_in[2];
    const float* b1   = (const float*)d_in[3];
    const float* W2   = (const float*)d_in[4];
    const float* b2   = (const float*)d_in[5];
    const float* temp = (const float*)d_in[6];
    float*       out  = (float*)d_out;

    __half *h1, *us;
    cudaGetSymbolAddress((void**)&h1, g_h1);
    cudaGetSymbolAddress((void**)&us, g_us);

    int mblocks = (N_NODES + 127) / 128;        // 782
    int pblocks = (N_NODES / 4 + 7) / 8;        // 4 rows/warp, 8 warps/block

    constexpr int SMEM1 = 3 * (128 * 36 * 4 + 32 * 136 * 4);  // 107520 (BN=128)
    constexpr int SMEM2 = 3 * (128 * 40 * 2 + 32 * 72 * 4);   // 58368  (BN=64)
    static bool attr_done = false;
    if (!attr_done) {
        cudaFuncSetAttribute(
            (const void*)tc_gemm_kernel<128, 8, true, false, true, true, false, true>,
            cudaFuncAttributeMaxDynamicSharedMemorySize, SMEM1);
        cudaFuncSetAttribute(
            (const void*)tc_gemm_kernel<64, 4, false, true, false, true, true, false>,
            cudaFuncAttributeMaxDynamicSharedMemorySize, SMEM2);
        attr_done = true;
    }

    // ---- fork: fill+build on side stream, concurrent with gemm1 ----
    cudaEventRecord(g_ss.evA, 0);
    cudaStreamWaitEvent(g_ss.s1, g_ss.evA, 0);
    fill_kernel<<<(N_NODES * SLOTS / 4 + 255) / 256, 256, 0, g_ss.s1>>>();
    build_kernel<<<(E_EDGES / 4 + 255) / 256, 256, 0, g_ss.s1>>>(ei);
    cudaEventRecord(g_ss.evB, g_ss.s1);

    // gemm1 (independent of graph state): x @ W1 (+relu) -> h1 fp16.
    // SWAP_GRID: grid=(2, 782) so the two N-block CTAs per row-block are
    // launch-adjacent -> second x read hits L2.
    tc_gemm_kernel<128, 8, true, false, true, true, false, true>
        <<<dim3(NHID / 128, mblocks), 256, SMEM1>>>(x, W1, b1, h1, nullptr,
                                                    N_NODES, NHID, NFEAT);

    // ---- join: gemm2's epilogue reads g_deg ----
    cudaStreamWaitEvent(0, g_ss.evB, 0);

    // gemm2: h1 @ W2 -> u0 = dinv * (h1@W2 + b2) in slab 0
    tc_gemm_kernel<64, 4, false, true, false, true, true, false>
        <<<dim3(mblocks, 1), 256, SMEM2>>>(h1, W2, b2, nullptr, us,
                                           N_NODES, NCLASS, NHID);
    // hops: slab k -> slab k+1
    for (int k = 0; k < K_HOPS; k++) {
        const __half* uin = us + (size_t)k * SLABSZ;
        __half*       uo  = us + (size_t)(k + 1) * SLABSZ;
        propagate_kernel<<<pblocks, 256>>>(uin, uo);
    }
    // weighted sum + scale + log_softmax
    finalize_kernel<<<(N_NODES * 32 + 255) / 256, 256>>>(temp, out);
}

// round 16
// speedup vs baseline: 1.0204x; 1.0204x over previous
#include <cuda_runtime.h>
#include <cuda_fp16.h>
#include <cstdint>

#define N_NODES 100000
#define E_EDGES 3200000
#define NFEAT   512
#define NHID    256
#define NCLASS  64
#define K_HOPS  10
#define SLOTS   96          // padded neighbor slots (Poisson(32); P(>96) ~ 1e-17/node)

#define SLABSZ  ((size_t)(N_NODES + 1) * NCLASS)   // halves per u-slab (+1 zero row)
#define ZOFF    (N_NODES * 128)                    // byte offset of the zero row

// ---------------- scratch (device globals) ----------------
__device__ __align__(256) __half g_h1[(size_t)N_NODES * NHID];        // 51.2 MB
__device__ __align__(256) __half g_us[(size_t)(K_HOPS + 1) * SLABSZ]; // u_k slabs
__device__ int g_deg[N_NODES];
__device__ __align__(16) int g_col[(size_t)N_NODES * SLOTS + 128];    // byte offsets

// ---------------- fill: pad all slots with zero-row offset; reset deg ----------
__global__ void fill_kernel() {
    int i = blockIdx.x * blockDim.x + threadIdx.x;
    const int n4 = N_NODES * SLOTS / 4;
    if (i < n4) ((int4*)g_col)[i] = make_int4(ZOFF, ZOFF, ZOFF, ZOFF);
    if (i < N_NODES) g_deg[i] = 0;
}

// ---------------- graph build: 4 edges per thread (int4 loads) ----------------
__global__ void build_kernel(const int* __restrict__ ei) {
    int e4 = (blockIdx.x * blockDim.x + threadIdx.x) * 4;
    if (e4 < E_EDGES) {
        int4 s = *(const int4*)&ei[e4];
        int4 d = *(const int4*)&ei[(size_t)E_EDGES + e4];
        int p;
        p = atomicAdd(&g_deg[d.x], 1);
        if (p < SLOTS) g_col[(size_t)d.x * SLOTS + p] = s.x << 7;
        p = atomicAdd(&g_deg[d.y], 1);
        if (p < SLOTS) g_col[(size_t)d.y * SLOTS + p] = s.y << 7;
        p = atomicAdd(&g_deg[d.z], 1);
        if (p < SLOTS) g_col[(size_t)d.z * SLOTS + p] = s.z << 7;
        p = atomicAdd(&g_deg[d.w], 1);
        if (p < SLOTS) g_col[(size_t)d.w * SLOTS + p] = s.w << 7;
    }
}

// ---------------- cp.async helpers ----------------
__device__ __forceinline__ void cpa16(uint32_t dst, const void* src, bool pred) {
    int sz = pred ? 16 : 0;
    asm volatile("cp.async.cg.shared.global [%0], [%1], 16, %2;\n"
                 :: "r"(dst), "l"(src), "r"(sz));
}
__device__ __forceinline__ void cpa_commit() {
    asm volatile("cp.async.commit_group;\n");
}
template <int N>
__device__ __forceinline__ void cpa_wait() {
    asm volatile("cp.async.wait_group %0;\n" :: "n"(N));
}
__device__ __forceinline__ uint32_t smem_u32(const void* p) {
    return (uint32_t)__cvta_generic_to_shared(p);
}

// ---------------- tf32 mma ----------------
__device__ __forceinline__ void mma_tf32(float* d, const unsigned* a,
                                         unsigned b0, unsigned b1) {
    asm volatile(
        "mma.sync.aligned.m16n8k8.row.col.f32.tf32.tf32.f32 "
        "{%0,%1,%2,%3},{%4,%5,%6,%7},{%8,%9},{%0,%1,%2,%3};"
        : "+f"(d[0]), "+f"(d[1]), "+f"(d[2]), "+f"(d[3])
        : "r"(a[0]), "r"(a[1]), "r"(a[2]), "r"(a[3]), "r"(b0), "r"(b1));
}

// ---------------- 3-stage cp.async tf32 GEMM ----------------
// SWAP_GRID: blockIdx.y selects the M-block, blockIdx.x the N-block. With
// grid=(Nblocks, Mblocks), the CTAs sharing an A-row-block are launch-adjacent
// and resident concurrently -> the second read of the A panel hits L2.
template <int BN, int NFRAG, bool RELU, bool A_HALF, bool WRITE_C, bool HALF_C,
          bool WRITE_U, bool SWAP_GRID>
__global__ __launch_bounds__(256) void tc_gemm_kernel(
    const void* __restrict__ Av, const float* __restrict__ B,
    const float* __restrict__ bias, void* __restrict__ Cv,
    __half* __restrict__ U, int M, int N, int K)
{
    constexpr int BM = 128, BK = 32;
    constexpr int ASTR  = A_HALF ? 40 : 36;
    constexpr int BSTR  = BN + 8;
    constexpr int ABYTES = BM * ASTR * (A_HALF ? 2 : 4);
    constexpr int BBYTES = BK * BSTR * 4;
    constexpr int STAGE  = ABYTES + BBYTES;
    extern __shared__ char dynsmem[];

    int tid  = threadIdx.x;
    int lane = tid & 31;
    int wid  = tid >> 5;
    int warpM = (wid & 3) * 32;
    int warpN = (wid >> 2) * (BN / 2);
    int blockRow = (SWAP_GRID ? blockIdx.y : blockIdx.x) * BM;
    int blockCol = (SWAP_GRID ? blockIdx.x : blockIdx.y) * BN;

    const float*  Af = (const float*)Av;
    const __half* Ah = (const __half*)Av;

    float acc[2][NFRAG][4];
    #pragma unroll
    for (int mf = 0; mf < 2; mf++)
        #pragma unroll
        for (int nf = 0; nf < NFRAG; nf++)
            #pragma unroll
            for (int j = 0; j < 4; j++) acc[mf][nf][j] = 0.f;

    const int T = K / BK;

    auto issue = [&](int s, int k0) {
        char* sb = dynsmem + s * STAGE;
        if (A_HALF) {
            __half* As = (__half*)sb;
            #pragma unroll
            for (int j = 0; j < 2; j++) {
                int id  = tid + 256 * j;
                int row = id >> 2, cc = id & 3;
                int grow = blockRow + row;
                cpa16(smem_u32(&As[row * ASTR + cc * 8]),
                      &Ah[(size_t)grow * K + k0 + cc * 8], grow < M);
            }
        } else {
            float* As = (float*)sb;
            #pragma unroll
            for (int j = 0; j < 4; j++) {
                int id  = tid + 256 * j;
                int row = id >> 3, cc = id & 7;
                int grow = blockRow + row;
                cpa16(smem_u32(&As[row * ASTR + cc * 4]),
                      &Af[(size_t)grow * K + k0 + cc * 4], grow < M);
            }
        }
        float* Bs = (float*)(sb + ABYTES);
        constexpr int cpr = BN / 4;
        constexpr int per = (BK * cpr) / 256;
        #pragma unroll
        for (int j = 0; j < per; j++) {
            int id  = tid + 256 * j;
            int row = id / cpr, cc = id % cpr;
            cpa16(smem_u32(&Bs[row * BSTR + cc * 4]),
                  &B[(size_t)(k0 + row) * N + blockCol + cc * 4], true);
        }
        cpa_commit();
    };

    issue(0, 0);
    issue(1, BK);

    int cur = 0;
    for (int t = 0; t < T; t++) {
        if (t + 1 == T) cpa_wait<0>(); else cpa_wait<1>();
        __syncthreads();
        if (t + 2 < T) {
            int nx = cur + 2; if (nx >= 3) nx -= 3;
            issue(nx, (t + 2) * BK);
        }

        char* sb = dynsmem + cur * STAGE;
        const __half* AsH = (const __half*)sb;
        const float*  AsF = (const float*)sb;
        const float*  Bs  = (const float*)(sb + ABYTES);

        #pragma unroll
        for (int ks = 0; ks < 4; ks++) {
            int kb = ks * 8;
            int ar = warpM + (lane >> 2);
            int ac = kb + (lane & 3);
            unsigned a[2][4];
            #pragma unroll
            for (int mf = 0; mf < 2; mf++) {
                int r = ar + mf * 16;
                if (A_HALF) {
                    a[mf][0] = __float_as_uint(__half2float(AsH[r * ASTR + ac]));
                    a[mf][1] = __float_as_uint(__half2float(AsH[(r + 8) * ASTR + ac]));
                    a[mf][2] = __float_as_uint(__half2float(AsH[r * ASTR + ac + 4]));
                    a[mf][3] = __float_as_uint(__half2float(AsH[(r + 8) * ASTR + ac + 4]));
                } else {
                    a[mf][0] = __float_as_uint(AsF[r * ASTR + ac]);
                    a[mf][1] = __float_as_uint(AsF[(r + 8) * ASTR + ac]);
                    a[mf][2] = __float_as_uint(AsF[r * ASTR + ac + 4]);
                    a[mf][3] = __float_as_uint(AsF[(r + 8) * ASTR + ac + 4]);
                }
            }
            int br = kb + (lane & 3);
            #pragma unroll
            for (int nf = 0; nf < NFRAG; nf++) {
                int bc = warpN + nf * 8 + (lane >> 2);
                unsigned b0 = __float_as_uint(Bs[br * BSTR + bc]);
                unsigned b1 = __float_as_uint(Bs[(br + 4) * BSTR + bc]);
                mma_tf32(acc[0][nf], a[0], b0, b1);
                mma_tf32(acc[1][nf], a[1], b0, b1);
            }
        }
        cur++; if (cur >= 3) cur -= 3;
    }

    #pragma unroll
    for (int mf = 0; mf < 2; mf++) {
        int row0 = blockRow + warpM + mf * 16 + (lane >> 2);
        float di0 = 0.f, di1 = 0.f;
        if (WRITE_U) {
            if (row0 < M)     di0 = rsqrtf((float)(g_deg[row0] + 1));
            if (row0 + 8 < M) di1 = rsqrtf((float)(g_deg[row0 + 8] + 1));
        }
        #pragma unroll
        for (int nf = 0; nf < NFRAG; nf++) {
            int col = blockCol + warpN + nf * 8 + 2 * (lane & 3);
            float2 bvx = __ldg((const float2*)&bias[col]);
            float2 o0, o1;
            o0.x = acc[mf][nf][0] + bvx.x; o0.y = acc[mf][nf][1] + bvx.y;
            o1.x = acc[mf][nf][2] + bvx.x; o1.y = acc[mf][nf][3] + bvx.y;
            if (RELU) {
                o0.x = fmaxf(o0.x, 0.f); o0.y = fmaxf(o0.y, 0.f);
                o1.x = fmaxf(o1.x, 0.f); o1.y = fmaxf(o1.y, 0.f);
            }
            if (WRITE_C) {
                if (HALF_C) {
                    __half* Ch = (__half*)Cv;
                    if (row0 < M)
                        *(__half2*)&Ch[(size_t)row0 * N + col] = __floats2half2_rn(o0.x, o0.y);
                    if (row0 + 8 < M)
                        *(__half2*)&Ch[(size_t)(row0 + 8) * N + col] = __floats2half2_rn(o1.x, o1.y);
                } else {
                    float* Cf = (float*)Cv;
                    if (row0 < M)     *(float2*)&Cf[(size_t)row0 * N + col]       = o0;
                    if (row0 + 8 < M) *(float2*)&Cf[(size_t)(row0 + 8) * N + col] = o1;
                }
            }
            if (WRITE_U) {
                if (row0 < M)
                    *(__half2*)&U[(size_t)row0 * N + col] =
                        __floats2half2_rn(di0 * o0.x, di0 * o0.y);
                if (row0 + 8 < M)
                    *(__half2*)&U[(size_t)(row0 + 8) * N + col] =
                        __floats2half2_rn(di1 * o1.x, di1 * o1.y);
            }
        }
    }
}

// ---------------- one hop: 4 rows per warp, uint4 per lane --------------------
__global__ __launch_bounds__(256) void propagate_kernel(
    const __half* __restrict__ uin, __half* __restrict__ uout)
{
    int gwarp = (blockIdx.x * blockDim.x + threadIdx.x) >> 5;
    int lane  = threadIdx.x & 31;
    int g     = lane >> 3;
    int lig   = lane & 7;
    int row   = gwarp * 4 + g;
    if (row >= N_NODES) return;

    int deg = g_deg[row];
    if (deg > SLOTS) deg = SLOTS;

    const char* base = (const char*)uin + lig * 16;

    uint4 sv = __ldg((const uint4*)(base + (size_t)row * 128));   // self term
    __half2 a0 = ((__half2*)&sv)[0], a1 = ((__half2*)&sv)[1];
    __half2 a2 = ((__half2*)&sv)[2], a3 = ((__half2*)&sv)[3];
    __half2 z  = __float2half2_rn(0.f);
    __half2 b0 = z, b1 = z, b2 = z, b3 = z;

    int md = deg;
    md = max(md, __shfl_xor_sync(0xffffffffu, md, 8));
    md = max(md, __shfl_xor_sync(0xffffffffu, md, 16));

    const int4* cp = (const int4*)&g_col[(size_t)row * SLOTS];
    int nchunks = (md + 3) >> 2;
    for (int c = 0; c < nchunks; c++) {
        int4 off = __ldg(&cp[c]);
        uint4 v0 = __ldg((const uint4*)(base + off.x));
        uint4 v1 = __ldg((const uint4*)(base + off.y));
        uint4 v2 = __ldg((const uint4*)(base + off.z));
        uint4 v3 = __ldg((const uint4*)(base + off.w));
        a0 = __hadd2(a0, ((__half2*)&v0)[0]); a1 = __hadd2(a1, ((__half2*)&v0)[1]);
        a2 = __hadd2(a2, ((__half2*)&v0)[2]); a3 = __hadd2(a3, ((__half2*)&v0)[3]);
        b0 = __hadd2(b0, ((__half2*)&v1)[0]); b1 = __hadd2(b1, ((__half2*)&v1)[1]);
        b2 = __hadd2(b2, ((__half2*)&v1)[2]); b3 = __hadd2(b3, ((__half2*)&v1)[3]);
        a0 = __hadd2(a0, ((__half2*)&v2)[0]); a1 = __hadd2(a1, ((__half2*)&v2)[1]);
        a2 = __hadd2(a2, ((__half2*)&v2)[2]); a3 = __hadd2(a3, ((__half2*)&v2)[3]);
        b0 = __hadd2(b0, ((__half2*)&v3)[0]); b1 = __hadd2(b1, ((__half2*)&v3)[1]);
        b2 = __hadd2(b2, ((__half2*)&v3)[2]); b3 = __hadd2(b3, ((__half2*)&v3)[3]);
    }

    __half2 di2 = __float2half2_rn(1.0f / (float)(deg + 1));
    uint4 ov;
    ((__half2*)&ov)[0] = __hmul2(__hadd2(a0, b0), di2);
    ((__half2*)&ov)[1] = __hmul2(__hadd2(a1, b1), di2);
    ((__half2*)&ov)[2] = __hmul2(__hadd2(a2, b2), di2);
    ((__half2*)&ov)[3] = __hmul2(__hadd2(a3, b3), di2);
    *(uint4*)((char*)uout + (size_t)row * 128 + lig * 16) = ov;
}

// ---------------- finalize: logits = sqrt(deg+1)*sum temp_k u_k; log_softmax ----
__global__ __launch_bounds__(256) void finalize_kernel(
    const float* __restrict__ temp, float* __restrict__ out)
{
    int gid  = blockIdx.x * blockDim.x + threadIdx.x;
    int row  = gid >> 5;
    int lane = gid & 31;
    if (row >= N_NODES) return;

    float sc = sqrtf((float)(g_deg[row] + 1));

    const __half2* us2 = (const __half2*)g_us;
    const size_t SLAB2 = SLABSZ / 2;
    float hx = 0.f, hy = 0.f;
    #pragma unroll
    for (int k = 0; k <= K_HOPS; k++) {
        float2 v = __half22float2(
            __ldg(&us2[(size_t)k * SLAB2 + (size_t)row * 32 + lane]));
        float t = __ldg(&temp[k]);
        hx += t * v.x; hy += t * v.y;
    }
    hx *= sc; hy *= sc;

    float m = fmaxf(hx, hy);
    #pragma unroll
    for (int o = 16; o; o >>= 1) m = fmaxf(m, __shfl_xor_sync(0xffffffffu, m, o));
    float s = expf(hx - m) + expf(hy - m);
    #pragma unroll
    for (int o = 16; o; o >>= 1) s += __shfl_xor_sync(0xffffffffu, s, o);
    float lse = m + logf(s);
    ((float2*)out)[(size_t)row * 32 + lane] = make_float2(hx - lse, hy - lse);
}

// ---------------- launch ----------------
extern "C" void kernel_launch(void* const* d_in, const int* in_sizes, int n_in,
                              void* d_out, int out_size) {
    const float* x    = (const float*)d_in[0];
    const int*   ei   = (const int*)d_in[1];    // int32 (JAX x64 disabled)
    const float* W1   = (const float*)d_in[2];
    const float* b1   = (const float*)d_in[3];
    const float* W2   = (const float*)d_in[4];
    const float* b2   = (const float*)d_in[5];
    const float* temp = (const float*)d_in[6];
    float*       out  = (float*)d_out;

    __half *h1, *us;
    cudaGetSymbolAddress((void**)&h1, g_h1);
    cudaGetSymbolAddress((void**)&us, g_us);

    int mblocks = (N_NODES + 127) / 128;        // 782
    int pblocks = (N_NODES / 4 + 7) / 8;        // 4 rows/warp, 8 warps/block

    constexpr int SMEM1 = 3 * (128 * 36 * 4 + 32 * 136 * 4);  // 107520 (BN=128)
    constexpr int SMEM2 = 3 * (128 * 40 * 2 + 32 * 72 * 4);   // 58368  (BN=64)
    static bool attr_done = false;
    if (!attr_done) {
        cudaFuncSetAttribute(
            (const void*)tc_gemm_kernel<128, 8, true, false, true, true, false, true>,
            cudaFuncAttributeMaxDynamicSharedMemorySize, SMEM1);
        cudaFuncSetAttribute(
            (const void*)tc_gemm_kernel<64, 4, false, true, false, true, true, false>,
            cudaFuncAttributeMaxDynamicSharedMemorySize, SMEM2);
        attr_done = true;
    }

    // 1. fill padded slots with zero-row offset; reset deg   (single stream)
    fill_kernel<<<(N_NODES * SLOTS / 4 + 255) / 256, 256>>>();
    // 2. build padded adjacency (int4 edge loads)
    build_kernel<<<(E_EDGES / 4 + 255) / 256, 256>>>(ei);
    // 3. gemm1: x @ W1 (+relu) -> h1 fp16.
    //    SWAP_GRID: grid=(2, 782) -> the two N-block CTAs per A-row-block are
    //    launch-adjacent, so the second x read hits L2 (single-variable test).
    tc_gemm_kernel<128, 8, true, false, true, true, false, true>
        <<<dim3(NHID / 128, mblocks), 256, SMEM1>>>(x, W1, b1, h1, nullptr,
                                                    N_NODES, NHID, NFEAT);
    // 4. gemm2: h1 @ W2 -> u0 = dinv * (h1@W2 + b2) in slab 0
    tc_gemm_kernel<64, 4, false, true, false, true, true, false>
        <<<dim3(mblocks, 1), 256, SMEM2>>>(h1, W2, b2, nullptr, us,
                                           N_NODES, NCLASS, NHID);
    // 5-14. hops: slab k -> slab k+1
    for (int k = 0; k < K_HOPS; k++) {
        const __half* uin = us + (size_t)k * SLABSZ;
        __half*       uo  = us + (size_t)(k + 1) * SLABSZ;
        propagate_kernel<<<pblocks, 256>>>(uin, uo);
    }
    // 15. weighted sum + scale + log_softmax
    finalize_kernel<<<(N_NODES * 32 + 255) / 256, 256>>>(temp, out);
}

// round 17
// speedup vs baseline: 1.0383x; 1.0176x over previous
#include <cuda_runtime.h>
#include <cuda_fp16.h>
#include <cstdint>

#define N_NODES 100000
#define E_EDGES 3200000
#define NFEAT   512
#define NHID    256
#define NCLASS  64
#define K_HOPS  10
#define SLOTS   96          // padded neighbor slots (Poisson(32); P(>96) ~ 1e-17/node)

#define SLABSZ  ((size_t)(N_NODES + 1) * NCLASS)   // halves per u-slab (+1 zero row)
#define ZOFF    (N_NODES * 128)                    // byte offset of the zero row

// ---------------- scratch (device globals) ----------------
__device__ __align__(256) __half g_h1[(size_t)N_NODES * NHID];        // 51.2 MB
__device__ __align__(256) __half g_us[(size_t)(K_HOPS + 1) * SLABSZ]; // u_k slabs
__device__ __align__(16)  __half g_w2h[NHID * NCLASS];                // fp16 W2
__device__ int g_deg[N_NODES];
__device__ __align__(16) int g_col[(size_t)N_NODES * SLOTS + 128];    // byte offsets

// ---------------- fill: pad all slots with zero-row offset; reset deg ----------
__global__ void fill_kernel() {
    int i = blockIdx.x * blockDim.x + threadIdx.x;
    const int n4 = N_NODES * SLOTS / 4;
    if (i < n4) ((int4*)g_col)[i] = make_int4(ZOFF, ZOFF, ZOFF, ZOFF);
    if (i < N_NODES) g_deg[i] = 0;
}

// ---------------- graph build: 4 edges per thread (int4 loads) ----------------
__global__ void build_kernel(const int* __restrict__ ei) {
    int e4 = (blockIdx.x * blockDim.x + threadIdx.x) * 4;
    if (e4 < E_EDGES) {
        int4 s = *(const int4*)&ei[e4];
        int4 d = *(const int4*)&ei[(size_t)E_EDGES + e4];
        int p;
        p = atomicAdd(&g_deg[d.x], 1);
        if (p < SLOTS) g_col[(size_t)d.x * SLOTS + p] = s.x << 7;
        p = atomicAdd(&g_deg[d.y], 1);
        if (p < SLOTS) g_col[(size_t)d.y * SLOTS + p] = s.y << 7;
        p = atomicAdd(&g_deg[d.z], 1);
        if (p < SLOTS) g_col[(size_t)d.z * SLOTS + p] = s.z << 7;
        p = atomicAdd(&g_deg[d.w], 1);
        if (p < SLOTS) g_col[(size_t)d.w * SLOTS + p] = s.w << 7;
    }
}

// ---------------- W2 fp32 -> fp16 ----------------
__global__ void w2cvt_kernel(const float* __restrict__ W2) {
    int i = blockIdx.x * blockDim.x + threadIdx.x;
    if (i < NHID * NCLASS) g_w2h[i] = __float2half(W2[i]);
}

// ---------------- cp.async / ldmatrix / mma helpers ----------------
__device__ __forceinline__ void cpa16(uint32_t dst, const void* src, bool pred) {
    int sz = pred ? 16 : 0;
    asm volatile("cp.async.cg.shared.global [%0], [%1], 16, %2;\n"
                 :: "r"(dst), "l"(src), "r"(sz));
}
__device__ __forceinline__ void cpa_commit() {
    asm volatile("cp.async.commit_group;\n");
}
template <int N>
__device__ __forceinline__ void cpa_wait() {
    asm volatile("cp.async.wait_group %0;\n" :: "n"(N));
}
__device__ __forceinline__ uint32_t smem_u32(const void* p) {
    return (uint32_t)__cvta_generic_to_shared(p);
}
__device__ __forceinline__ void ldsm_x4(unsigned* d, uint32_t addr) {
    asm volatile("ldmatrix.sync.aligned.m8n8.x4.shared.b16 {%0,%1,%2,%3}, [%4];"
                 : "=r"(d[0]), "=r"(d[1]), "=r"(d[2]), "=r"(d[3]) : "r"(addr));
}
__device__ __forceinline__ void ldsm_x4_trans(unsigned* d, uint32_t addr) {
    asm volatile("ldmatrix.sync.aligned.m8n8.x4.trans.shared.b16 {%0,%1,%2,%3}, [%4];"
                 : "=r"(d[0]), "=r"(d[1]), "=r"(d[2]), "=r"(d[3]) : "r"(addr));
}
__device__ __forceinline__ void mma_tf32(float* d, const unsigned* a,
                                         unsigned b0, unsigned b1) {
    asm volatile(
        "mma.sync.aligned.m16n8k8.row.col.f32.tf32.tf32.f32 "
        "{%0,%1,%2,%3},{%4,%5,%6,%7},{%8,%9},{%0,%1,%2,%3};"
        : "+f"(d[0]), "+f"(d[1]), "+f"(d[2]), "+f"(d[3])
        : "r"(a[0]), "r"(a[1]), "r"(a[2]), "r"(a[3]), "r"(b0), "r"(b1));
}
__device__ __forceinline__ void mma_f16(float* d, const unsigned* a,
                                        unsigned b0, unsigned b1) {
    asm volatile(
        "mma.sync.aligned.m16n8k16.row.col.f32.f16.f16.f32 "
        "{%0,%1,%2,%3},{%4,%5,%6,%7},{%8,%9},{%0,%1,%2,%3};"
        : "+f"(d[0]), "+f"(d[1]), "+f"(d[2]), "+f"(d[3])
        : "r"(a[0]), "r"(a[1]), "r"(a[2]), "r"(a[3]), "r"(b0), "r"(b1));
}

// ---------------- gemm1: tf32, A-frags via ldmatrix (b16 trick) -----------------
// h1[M,256] = relu(x[M,512] @ W1 + b1), fp16 out. BM=128,BN=128,BK=32, 3 stages.
__global__ __launch_bounds__(256) void gemm1_kernel(
    const float* __restrict__ A, const float* __restrict__ B,
    const float* __restrict__ bias, __half* __restrict__ C)
{
    constexpr int BM = 128, BN = 128, BK = 32;
    constexpr int ASTR = 36, BSTR = BN + 8;              // floats
    constexpr int ABYTES = BM * ASTR * 4;                // 18432
    constexpr int BBYTES = BK * BSTR * 4;                // 17408
    constexpr int STAGE  = ABYTES + BBYTES;
    const int M = N_NODES, N = NHID, K = NFEAT;
    extern __shared__ char dynsmem[];

    int tid  = threadIdx.x;
    int lane = tid & 31;
    int wid  = tid >> 5;
    int warpM = (wid & 3) * 32;
    int warpN = (wid >> 2) * 64;
    int blockRow = blockIdx.y * BM;                      // SWAP_GRID semantics
    int blockCol = blockIdx.x * BN;

    float acc[2][8][4];
    #pragma unroll
    for (int mf = 0; mf < 2; mf++)
        #pragma unroll
        for (int nf = 0; nf < 8; nf++)
            #pragma unroll
            for (int j = 0; j < 4; j++) acc[mf][nf][j] = 0.f;

    const int T = K / BK;                                // 16

    auto issue = [&](int s, int k0) {
        char* sb = dynsmem + s * STAGE;
        float* As = (float*)sb;
        #pragma unroll
        for (int j = 0; j < 4; j++) {
            int id  = tid + 256 * j;
            int row = id >> 3, cc = id & 7;
            int grow = blockRow + row;
            cpa16(smem_u32(&As[row * ASTR + cc * 4]),
                  &A[(size_t)grow * K + k0 + cc * 4], grow < M);
        }
        float* Bs = (float*)(sb + ABYTES);
        #pragma unroll
        for (int j = 0; j < 4; j++) {                    // 32 rows x 32 chunks
            int id  = tid + 256 * j;
            int row = id >> 5, cc = id & 31;
            cpa16(smem_u32(&Bs[row * BSTR + cc * 4]),
                  &B[(size_t)(k0 + row) * N + blockCol + cc * 4], true);
        }
        cpa_commit();
    };

    issue(0, 0);
    issue(1, BK);

    int q = lane >> 3, rr = lane & 7;                    // ldmatrix lane roles
    int cur = 0;
    for (int t = 0; t < T; t++) {
        if (t + 1 == T) cpa_wait<0>(); else cpa_wait<1>();
        __syncthreads();
        if (t + 2 < T) {
            int nx = cur + 2; if (nx >= 3) nx -= 3;
            issue(nx, (t + 2) * BK);
        }

        char* sb = dynsmem + cur * STAGE;
        const float* Bs = (const float*)(sb + ABYTES);
        // per-lane ldmatrix base (mf=0): quadrants = (q&1)*8 rows, (q>>1)*4 tf32 cols
        uint32_t aaddr = smem_u32(sb) +
            (uint32_t)(((warpM + (q & 1) * 8 + rr) * ASTR + (q >> 1) * 4) * 4);

        #pragma unroll
        for (int ks = 0; ks < 4; ks++) {
            unsigned a[2][4];
            ldsm_x4(a[0], aaddr + ks * 32);
            ldsm_x4(a[1], aaddr + 16 * ASTR * 4 + ks * 32);
            int br = ks * 8 + (lane & 3);
            #pragma unroll
            for (int nf = 0; nf < 8; nf++) {
                int bc = warpN + nf * 8 + (lane >> 2);
                unsigned b0 = __float_as_uint(Bs[br * BSTR + bc]);
                unsigned b1 = __float_as_uint(Bs[(br + 4) * BSTR + bc]);
                mma_tf32(acc[0][nf], a[0], b0, b1);
                mma_tf32(acc[1][nf], a[1], b0, b1);
            }
        }
        cur++; if (cur >= 3) cur -= 3;
    }

    #pragma unroll
    for (int mf = 0; mf < 2; mf++) {
        int row0 = blockRow + warpM + mf * 16 + (lane >> 2);
        #pragma unroll
        for (int nf = 0; nf < 8; nf++) {
            int col = blockCol + warpN + nf * 8 + 2 * (lane & 3);
            float2 bvx = __ldg((const float2*)&bias[col]);
            float2 o0, o1;
            o0.x = fmaxf(acc[mf][nf][0] + bvx.x, 0.f);
            o0.y = fmaxf(acc[mf][nf][1] + bvx.y, 0.f);
            o1.x = fmaxf(acc[mf][nf][2] + bvx.x, 0.f);
            o1.y = fmaxf(acc[mf][nf][3] + bvx.y, 0.f);
            if (row0 < M)
                *(__half2*)&C[(size_t)row0 * N + col] = __floats2half2_rn(o0.x, o0.y);
            if (row0 + 8 < M)
                *(__half2*)&C[(size_t)(row0 + 8) * N + col] = __floats2half2_rn(o1.x, o1.y);
        }
    }
}

// ---------------- gemm2: fp16 m16n8k16, ldmatrix A + trans-ldmatrix B ----------
// u0[M,64] = rsqrt(deg+1) * (h1[M,256] @ W2h + b2), fp16 out.
__global__ __launch_bounds__(256) void gemm2_f16_kernel(
    const __half* __restrict__ A, const __half* __restrict__ B,
    const float* __restrict__ bias, __half* __restrict__ U)
{
    constexpr int BM = 128, BN = 64, BK = 32;
    constexpr int ASTR = 40, BSTR = 72;                  // halves
    constexpr int ABYTES = BM * ASTR * 2;                // 10240
    constexpr int BBYTES = BK * BSTR * 2;                // 4608
    constexpr int STAGE  = ABYTES + BBYTES;              // 14848
    const int M = N_NODES, N = NCLASS, K = NHID;
    extern __shared__ char dynsmem[];

    int tid  = threadIdx.x;
    int lane = tid & 31;
    int wid  = tid >> 5;
    int warpM = (wid & 3) * 32;
    int warpN = (wid >> 2) * 32;
    int blockRow = blockIdx.x * BM;

    float acc[2][4][4];
    #pragma unroll
    for (int mf = 0; mf < 2; mf++)
        #pragma unroll
        for (int nf = 0; nf < 4; nf++)
            #pragma unroll
            for (int j = 0; j < 4; j++) acc[mf][nf][j] = 0.f;

    const int T = K / BK;                                // 8

    auto issue = [&](int s, int k0) {
        char* sb = dynsmem + s * STAGE;
        __half* As = (__half*)sb;
        #pragma unroll
        for (int j = 0; j < 2; j++) {                    // 512 chunks
            int id  = tid + 256 * j;
            int row = id >> 2, cc = id & 3;
            int grow = blockRow + row;
            cpa16(smem_u32(&As[row * ASTR + cc * 8]),
                  &A[(size_t)grow * K + k0 + cc * 8], grow < M);
        }
        __half* Bs = (__half*)(sb + ABYTES);
        {                                                // 256 chunks, 1/thread
            int row = tid >> 3, cc = tid & 7;
            cpa16(smem_u32(&Bs[row * BSTR + cc * 8]),
                  &B[(size_t)(k0 + row) * N + cc * 8], true);
        }
        cpa_commit();
    };

    issue(0, 0);
    issue(1, BK);

    int q = lane >> 3, rr = lane & 7;
    int cur = 0;
    for (int t = 0; t < T; t++) {
        if (t + 1 == T) cpa_wait<0>(); else cpa_wait<1>();
        __syncthreads();
        if (t + 2 < T) {
            int nx = cur + 2; if (nx >= 3) nx -= 3;
            issue(nx, (t + 2) * BK);
        }

        char* sb = dynsmem + cur * STAGE;
        // A base: quadrants = (q&1)*8 rows, (q>>1)*8 k-halves
        uint32_t aaddr = smem_u32(sb) +
            (uint32_t)(((warpM + (q & 1) * 8 + rr) * ASTR + (q >> 1) * 8) * 2);
        // B base: matrices = (q&1)*8 k-rows, (q>>1)*8 n-halves (within pair)
        uint32_t baddr = smem_u32(sb + ABYTES) +
            (uint32_t)((((q & 1) * 8 + rr) * BSTR + warpN + (q >> 1) * 8) * 2);

        #pragma unroll
        for (int ks = 0; ks < 2; ks++) {                 // two k16 steps
            unsigned a[2][4];
            ldsm_x4(a[0], aaddr + ks * 32);                      // +16 halves
            ldsm_x4(a[1], aaddr + 16 * ASTR * 2 + ks * 32);
            unsigned b01[4], b23[4];
            ldsm_x4_trans(b01, baddr + ks * 16 * BSTR * 2);      // nf 0,1
            ldsm_x4_trans(b23, baddr + ks * 16 * BSTR * 2 + 32); // nf 2,3 (+16 n)
            mma_f16(acc[0][0], a[0], b01[0], b01[1]);
            mma_f16(acc[1][0], a[1], b01[0], b01[1]);
            mma_f16(acc[0][1], a[0], b01[2], b01[3]);
            mma_f16(acc[1][1], a[1], b01[2], b01[3]);
            mma_f16(acc[0][2], a[0], b23[0], b23[1]);
            mma_f16(acc[1][2], a[1], b23[0], b23[1]);
            mma_f16(acc[0][3], a[0], b23[2], b23[3]);
            mma_f16(acc[1][3], a[1], b23[2], b23[3]);
        }
        cur++; if (cur >= 3) cur -= 3;
    }

    #pragma unroll
    for (int mf = 0; mf < 2; mf++) {
        int row0 = blockRow + warpM + mf * 16 + (lane >> 2);
        float di0 = 0.f, di1 = 0.f;
        if (row0 < M)     di0 = rsqrtf((float)(g_deg[row0] + 1));
        if (row0 + 8 < M) di1 = rsqrtf((float)(g_deg[row0 + 8] + 1));
        #pragma unroll
        for (int nf = 0; nf < 4; nf++) {
            int col = warpN + nf * 8 + 2 * (lane & 3);
            float2 bvx = __ldg((const float2*)&bias[col]);
            float o0x = acc[mf][nf][0] + bvx.x, o0y = acc[mf][nf][1] + bvx.y;
            float o1x = acc[mf][nf][2] + bvx.x, o1y = acc[mf][nf][3] + bvx.y;
            if (row0 < M)
                *(__half2*)&U[(size_t)row0 * N + col] =
                    __floats2half2_rn(di0 * o0x, di0 * o0y);
            if (row0 + 8 < M)
                *(__half2*)&U[(size_t)(row0 + 8) * N + col] =
                    __floats2half2_rn(di1 * o1x, di1 * o1y);
        }
    }
}

// ---------------- one hop: 4 rows per warp, uint4 per lane --------------------
__global__ __launch_bounds__(256) void propagate_kernel(
    const __half* __restrict__ uin, __half* __restrict__ uout)
{
    int gwarp = (blockIdx.x * blockDim.x + threadIdx.x) >> 5;
    int lane  = threadIdx.x & 31;
    int g     = lane >> 3;
    int lig   = lane & 7;
    int row   = gwarp * 4 + g;
    if (row >= N_NODES) return;

    int deg = g_deg[row];
    if (deg > SLOTS) deg = SLOTS;

    const char* base = (const char*)uin + lig * 16;

    uint4 sv = __ldg((const uint4*)(base + (size_t)row * 128));   // self term
    __half2 a0 = ((__half2*)&sv)[0], a1 = ((__half2*)&sv)[1];
    __half2 a2 = ((__half2*)&sv)[2], a3 = ((__half2*)&sv)[3];
    __half2 z  = __float2half2_rn(0.f);
    __half2 b0 = z, b1 = z, b2 = z, b3 = z;

    int md = deg;
    md = max(md, __shfl_xor_sync(0xffffffffu, md, 8));
    md = max(md, __shfl_xor_sync(0xffffffffu, md, 16));

    const int4* cp = (const int4*)&g_col[(size_t)row * SLOTS];
    int nchunks = (md + 3) >> 2;
    for (int c = 0; c < nchunks; c++) {
        int4 off = __ldg(&cp[c]);
        uint4 v0 = __ldg((const uint4*)(base + off.x));
        uint4 v1 = __ldg((const uint4*)(base + off.y));
        uint4 v2 = __ldg((const uint4*)(base + off.z));
        uint4 v3 = __ldg((const uint4*)(base + off.w));
        a0 = __hadd2(a0, ((__half2*)&v0)[0]); a1 = __hadd2(a1, ((__half2*)&v0)[1]);
        a2 = __hadd2(a2, ((__half2*)&v0)[2]); a3 = __hadd2(a3, ((__half2*)&v0)[3]);
        b0 = __hadd2(b0, ((__half2*)&v1)[0]); b1 = __hadd2(b1, ((__half2*)&v1)[1]);
        b2 = __hadd2(b2, ((__half2*)&v1)[2]); b3 = __hadd2(b3, ((__half2*)&v1)[3]);
        a0 = __hadd2(a0, ((__half2*)&v2)[0]); a1 = __hadd2(a1, ((__half2*)&v2)[1]);
        a2 = __hadd2(a2, ((__half2*)&v2)[2]); a3 = __hadd2(a3, ((__half2*)&v2)[3]);
        b0 = __hadd2(b0, ((__half2*)&v3)[0]); b1 = __hadd2(b1, ((__half2*)&v3)[1]);
        b2 = __hadd2(b2, ((__half2*)&v3)[2]); b3 = __hadd2(b3, ((__half2*)&v3)[3]);
    }

    __half2 di2 = __float2half2_rn(1.0f / (float)(deg + 1));
    uint4 ov;
    ((__half2*)&ov)[0] = __hmul2(__hadd2(a0, b0), di2);
    ((__half2*)&ov)[1] = __hmul2(__hadd2(a1, b1), di2);
    ((__half2*)&ov)[2] = __hmul2(__hadd2(a2, b2), di2);
    ((__half2*)&ov)[3] = __hmul2(__hadd2(a3, b3), di2);
    *(uint4*)((char*)uout + (size_t)row * 128 + lig * 16) = ov;
}

// ---------------- finalize: logits = sqrt(deg+1)*sum temp_k u_k; log_softmax ----
__global__ __launch_bounds__(256) void finalize_kernel(
    const float* __restrict__ temp, float* __restrict__ out)
{
    int gid  = blockIdx.x * blockDim.x + threadIdx.x;
    int row  = gid >> 5;
    int lane = gid & 31;
    if (row >= N_NODES) return;

    float sc = sqrtf((float)(g_deg[row] + 1));

    const __half2* us2 = (const __half2*)g_us;
    const size_t SLAB2 = SLABSZ / 2;
    float hx = 0.f, hy = 0.f;
    #pragma unroll
    for (int k = 0; k <= K_HOPS; k++) {
        float2 v = __half22float2(
            __ldg(&us2[(size_t)k * SLAB2 + (size_t)row * 32 + lane]));
        float t = __ldg(&temp[k]);
        hx += t * v.x; hy += t * v.y;
    }
    hx *= sc; hy *= sc;

    float m = fmaxf(hx, hy);
    #pragma unroll
    for (int o = 16; o; o >>= 1) m = fmaxf(m, __shfl_xor_sync(0xffffffffu, m, o));
    float s = expf(hx - m) + expf(hy - m);
    #pragma unroll
    for (int o = 16; o; o >>= 1) s += __shfl_xor_sync(0xffffffffu, s, o);
    float lse = m + logf(s);
    ((float2*)out)[(size_t)row * 32 + lane] = make_float2(hx - lse, hy - lse);
}

// ---------------- launch ----------------
extern "C" void kernel_launch(void* const* d_in, const int* in_sizes, int n_in,
                              void* d_out, int out_size) {
    const float* x    = (const float*)d_in[0];
    const int*   ei   = (const int*)d_in[1];    // int32 (JAX x64 disabled)
    const float* W1   = (const float*)d_in[2];
    const float* b1   = (const float*)d_in[3];
    const float* W2   = (const float*)d_in[4];
    const float* b2   = (const float*)d_in[5];
    const float* temp = (const float*)d_in[6];
    float*       out  = (float*)d_out;

    __half *h1, *us, *w2h;
    cudaGetSymbolAddress((void**)&h1,  g_h1);
    cudaGetSymbolAddress((void**)&us,  g_us);
    cudaGetSymbolAddress((void**)&w2h, g_w2h);

    int mblocks = (N_NODES + 127) / 128;        // 782
    int pblocks = (N_NODES / 4 + 7) / 8;        // 4 rows/warp, 8 warps/block

    constexpr int SMEM1 = 3 * (128 * 36 * 4 + 32 * 136 * 4);  // 107520
    constexpr int SMEM2 = 3 * (128 * 40 * 2 + 32 * 72 * 2);   // 44544
    static bool attr_done = false;
    if (!attr_done) {
        cudaFuncSetAttribute((const void*)gemm1_kernel,
            cudaFuncAttributeMaxDynamicSharedMemorySize, SMEM1);
        cudaFuncSetAttribute((const void*)gemm2_f16_kernel,
            cudaFuncAttributeMaxDynamicSharedMemorySize, SMEM2);
        attr_done = true;
    }

    // 1. fill padded slots with zero-row offset; reset deg
    fill_kernel<<<(N_NODES * SLOTS / 4 + 255) / 256, 256>>>();
    // 2. build padded adjacency (int4 edge loads)
    build_kernel<<<(E_EDGES / 4 + 255) / 256, 256>>>(ei);
    // 3. W2 -> fp16 (tiny)
    w2cvt_kernel<<<(NHID * NCLASS + 255) / 256, 256>>>(W2);
    // 4. gemm1: tf32 + A-ldmatrix, grid=(2,782) launch-adjacent N-blocks
    gemm1_kernel<<<dim3(NHID / 128, mblocks), 256, SMEM1>>>(x, W1, b1, h1);
    // 5. gemm2: fp16 m16n8k16 -> u0 in slab 0
    gemm2_f16_kernel<<<mblocks, 256, SMEM2>>>(h1, w2h, b2, us);
    // 6-15. hops: slab k -> slab k+1
    for (int k = 0; k < K_HOPS; k++) {
        const __half* uin = us + (size_t)k * SLABSZ;
        __half*       uo  = us + (size_t)(k + 1) * SLABSZ;
        propagate_kernel<<<pblocks, 256>>>(uin, uo);
    }
    // 16. weighted sum + scale + log_softmax
    finalize_kernel<<<(N_NODES * 32 + 255) / 256, 256>>>(temp, out);
}